// round 12
// baseline (speedup 1.0000x reference)
#include <cuda_runtime.h>
#include <cstdint>

#define B_   16
#define CIN  256
#define CR   32
#define HW   4096          // 64*64
#define COUT 560           // 32 + 528

// 16 MB scratch: two K-half partial sums of the 1x1 conv (BN-scale folded,
// bias/ReLU deferred to k_head)
__device__ float g_zp[2][B_ * CR * HW];

__device__ __forceinline__ unsigned long long pack2(float lo, float hi) {
    unsigned long long r;
    asm("mov.b64 %0, {%1, %2};" : "=l"(r) : "r"(__float_as_uint(lo)), "r"(__float_as_uint(hi)));
    return r;
}
__device__ __forceinline__ unsigned long long fma2(unsigned long long a,
                                                   unsigned long long b,
                                                   unsigned long long c) {
    unsigned long long d;
    asm("fma.rn.f32x2 %0, %1, %2, %3;" : "=l"(d) : "l"(a), "l"(b), "l"(c));
    return d;
}
__device__ __forceinline__ void unpack2(unsigned long long v, float& lo, float& hi) {
    unsigned int l, h;
    asm("mov.b64 {%0, %1}, %2;" : "=r"(l), "=r"(h) : "l"(v));
    lo = __uint_as_float(l);
    hi = __uint_as_float(h);
}

// ---------------------------------------------------------------------------
// Kernel 1: 1x1 reduce conv, K-split 2.
// 128 threads = 2 channel-halves x 64 slots; thread = 16 out-ch x 4 ADJACENT
// pixels (LDG.128).  4 LDS.128 per 32 FFMA2 (2x density vs R4), STG.128 out.
// grid (256, 2).  Natural register allocation (~88), no occupancy clamp.
// ---------------------------------------------------------------------------
__global__ __launch_bounds__(128) void k_reduce(
    const float* __restrict__ x, const float* __restrict__ w,
    const float* __restrict__ gamma, const float* __restrict__ var)
{
    __shared__ __align__(16) float wsm[128 * CR];  // [c_local][o], BN inv folded
    __shared__ float inv_s[CR];

    const int tid = threadIdx.x;
    const int kh  = blockIdx.y;            // input channels kh*128 .. +128

    if (tid < CR)
        inv_s[tid] = gamma[tid] * rsqrtf(var[tid] + 1e-5f);
    __syncthreads();
    for (int i = tid; i < 128 * CR; i += 128) {
        int c = i >> 5, o = i & 31;        // c local
        wsm[i] = w[o * CIN + kh * 128 + c] * inv_s[o];
    }
    __syncthreads();

    const int h    = tid >> 6;             // channel half (warp-uniform)
    const int slot = tid & 63;             // 4-px slot
    const int base = blockIdx.x * 256;     // 256 pixels per block
    const int b    = base >> 12;           // 16 blocks per image
    const int s0   = (base & 4095) + slot * 4;

    const float* xp = x + ((size_t)(b * CIN + kh * 128) << 12) + s0;

    unsigned long long acc[4][8];          // [px][q]  (16 out-ch as 8 f32x2)
#pragma unroll
    for (int k = 0; k < 4; k++)
#pragma unroll
        for (int m = 0; m < 8; m++) acc[k][m] = 0ull;

#pragma unroll 4
    for (int c = 0; c < 128; c++) {
        float4 a = *reinterpret_cast<const float4*>(xp + (c << 12));  // LDG.128
        unsigned long long a2[4];
        a2[0] = pack2(a.x, a.x);
        a2[1] = pack2(a.y, a.y);
        a2[2] = pack2(a.z, a.z);
        a2[3] = pack2(a.w, a.w);
        const ulonglong2* wr =
            reinterpret_cast<const ulonglong2*>(wsm + c * CR + h * 16);
#pragma unroll
        for (int q = 0; q < 4; q++) {
            ulonglong2 w2 = wr[q];          // 4 output channels (2 f32x2)
#pragma unroll
            for (int k = 0; k < 4; k++) {
                acc[k][2 * q]     = fma2(a2[k], w2.x, acc[k][2 * q]);
                acc[k][2 * q + 1] = fma2(a2[k], w2.y, acc[k][2 * q + 1]);
            }
        }
    }

    float* zp = g_zp[kh] + ((size_t)(b * CR) << 12) + s0;
#pragma unroll
    for (int m = 0; m < 8; m++) {
        float v0[4], v1[4];
#pragma unroll
        for (int k = 0; k < 4; k++) unpack2(acc[k][m], v0[k], v1[k]);
        const int ch = h * 16 + 2 * m;
        *reinterpret_cast<float4*>(zp + ((size_t)ch << 12)) =
            make_float4(v0[0], v0[1], v0[2], v0[3]);
        *reinterpret_cast<float4*>(zp + ((size_t)(ch + 1) << 12)) =
            make_float4(v1[0], v1[1], v1[2], v1[3]);
    }
}

// ---------------------------------------------------------------------------
// Kernel 2 (measured 32.1us, unchanged): combine K-halves + bias + ReLU,
// depthwise 3x3 + scale, dual L2-normalize, triu pairs, concat.
// 32x4 pixel tile, 256 threads.
// ---------------------------------------------------------------------------
#define TW 32
#define TH 4
#define ROWW 34                       // TW + 2 halo
#define NPX  204                      // 6 * 34 halo'd pixels per channel
#define CH_STRIDE NPX

__global__ __launch_bounds__(256, 4) void k_head(
    const float* __restrict__ gamma, const float* __restrict__ beta,
    const float* __restrict__ mean,  const float* __restrict__ var,
    const float* __restrict__ dw,    const float* __restrict__ scale,
    float* __restrict__ out)
{
    __shared__ float zt[CR * CH_STRIDE];     // relu'd z tile with halo (25.5KB)
    __shared__ __align__(16) float zc_s[CR * 128];  // conv*scale per pixel (16KB)
    __shared__ float ssz_s[2][128];
    __shared__ float sst_s[2][128];
    __shared__ __align__(16) float invz_s[128];
    __shared__ __align__(16) float invt_s[128];
    __shared__ float dws[CR * 9];
    __shared__ float sc_s[CR];
    __shared__ float bias_s[CR];

    const int tid  = threadIdx.x;
    const int lane = tid & 31;
    const int wid  = tid >> 5;
    const int b    = blockIdx.z;
    const int ty0  = blockIdx.y * TH;
    const int tx0  = blockIdx.x * TW;
    const int half = tid >> 7;               // 0 or 1
    const int p    = tid & 127;              // pixel within tile
    const int pty  = p >> 5;
    const int ptx  = p & 31;

    if (tid < CR) {
        float inv = gamma[tid] * rsqrtf(var[tid] + 1e-5f);
        bias_s[tid] = beta[tid] - mean[tid] * inv;
        sc_s[tid]   = scale[tid];
    }
    for (int i = tid; i < CR * 9; i += 256) dws[i] = dw[i];
    __syncthreads();   // bias_s ready before tile load

    // ---- tile load: warp `wid` handles channels wid, wid+8, wid+16, wid+24 ----
    int  offs[7];
    bool vld[7];
#pragma unroll
    for (int it = 0; it < 7; it++) {
        int px = it * 32 + lane;             // 0..223, valid < NPX
        int y  = px / ROWW;
        int xx = px - y * ROWW;
        int gy = ty0 - 1 + y;
        int gx = tx0 - 1 + xx;
        vld[it]  = (px < NPX) && ((unsigned)gy < 64u) && ((unsigned)gx < 64u);
        offs[it] = (gy << 6) + gx;
    }
    const float* z0 = g_zp[0] + (((size_t)(b * CR)) << 12);
    const float* z1 = g_zp[1] + (((size_t)(b * CR)) << 12);
#pragma unroll
    for (int cc = 0; cc < 4; cc++) {
        const int c = cc * 8 + wid;
        const float* zc0 = z0 + ((size_t)c << 12);
        const float* zc1 = z1 + ((size_t)c << 12);
        const float bc = bias_s[c];
        float* st = zt + c * CH_STRIDE;
#pragma unroll
        for (int it = 0; it < 7; it++) {
            float v = 0.f;
            if (vld[it])
                v = fmaxf(__ldg(zc0 + offs[it]) + __ldg(zc1 + offs[it]) + bc, 0.f);
            int px = it * 32 + lane;
            if (px < NPX) st[px] = v;
        }
    }
    __syncthreads();

    // ---- conv: each thread does 16 channels for its pixel ----
    {
        float ssz = 0.f, sst = 0.f;
        const int cBase = half * 16;
#pragma unroll
        for (int cc = 0; cc < 16; cc++) {
            const int c = cBase + cc;
            const float* pp = zt + c * CH_STRIDE + pty * ROWW + ptx;
            const float* k9 = dws + c * 9;
            float acc;
            acc = pp[0] * k9[0];
            acc = fmaf(pp[1],            k9[1], acc);
            acc = fmaf(pp[2],            k9[2], acc);
            acc = fmaf(pp[ROWW],         k9[3], acc);
            float ctr = pp[ROWW + 1];
            acc = fmaf(ctr,              k9[4], acc);
            acc = fmaf(pp[ROWW + 2],     k9[5], acc);
            acc = fmaf(pp[2 * ROWW],     k9[6], acc);
            acc = fmaf(pp[2 * ROWW + 1], k9[7], acc);
            acc = fmaf(pp[2 * ROWW + 2], k9[8], acc);
            acc *= sc_s[c];
            zc_s[c * 128 + p] = acc;
            ssz = fmaf(ctr, ctr, ssz);
            sst = fmaf(acc, acc, sst);
        }
        ssz_s[half][p] = ssz;
        sst_s[half][p] = sst;
    }
    __syncthreads();

    {
        const float fz = ssz_s[0][p] + ssz_s[1][p];
        const float ft = sst_s[0][p] + sst_s[1][p];
        invz_s[p] = 1.f / fmaxf(sqrtf(fz), 1e-6f);
        invt_s[p] = 1.f / fmaxf(sqrtf(ft), 1e-6f);
    }
    __syncthreads();

    // ---- emit: warp e -> output channels [70e, 70e+70), lane -> 4-px group ----
    const int e  = wid;
    const int g  = lane;
    const int gy = g >> 3;
    const int gx = (g & 7) * 4;
    const int p0 = gy * 32 + gx;

    const float4 iz4 = *reinterpret_cast<const float4*>(&invz_s[p0]);
    const float4 it4 = *reinterpret_cast<const float4*>(&invt_s[p0]);

    const int s = ((ty0 + gy) << 6) + tx0 + gx;
    float* op = out + (size_t)b * COUT * HW + s;
    const float* ctr = zt + gy * ROWW + gx + ROWW + 1;   // + c*CH_STRIDE

    int ch = 70 * e;
    const int chHi = ch + 70;

    for (; ch < 32 && ch < chHi; ch++) {
        const float* zz = ctr + ch * CH_STRIDE;
        float4 o;
        o.x = zz[0] * iz4.x;
        o.y = zz[1] * iz4.y;
        o.z = zz[2] * iz4.z;
        o.w = zz[3] * iz4.w;
        *reinterpret_cast<float4*>(op + (size_t)ch * HW) = o;
    }

    if (ch < chHi) {
        int k = ch - 32;
        int i = 0;
        while (32 * (i + 1) - ((i + 1) * i) / 2 <= k) i++;
        int j = i + (k - (32 * i - (i * (i - 1)) / 2));

        float4 s4;
        s4.x = iz4.x * it4.x;
        s4.y = iz4.y * it4.y;
        s4.z = iz4.z * it4.z;
        s4.w = iz4.w * it4.w;

        const float* zz = ctr + i * CH_STRIDE;
        float4 zin;
        zin.x = zz[0] * s4.x;
        zin.y = zz[1] * s4.y;
        zin.z = zz[2] * s4.z;
        zin.w = zz[3] * s4.w;

        float* pdst = op + (size_t)ch * HW;
#pragma unroll 4
        for (; ch < chHi; ch++) {
            float4 zj = *reinterpret_cast<const float4*>(&zc_s[j * 128 + p0]);
            float4 o;
            o.x = zin.x * zj.x;
            o.y = zin.y * zj.y;
            o.z = zin.z * zj.z;
            o.w = zin.w * zj.w;
            *reinterpret_cast<float4*>(pdst) = o;
            pdst += HW;
            if (++j == CR) {
                ++i;
                j = i;
                if (i < CR) {
                    const float* z2 = ctr + i * CH_STRIDE;
                    zin.x = z2[0] * s4.x;
                    zin.y = z2[1] * s4.y;
                    zin.z = z2[2] * s4.z;
                    zin.w = z2[3] * s4.w;
                }
            }
        }
    }
}

extern "C" void kernel_launch(void* const* d_in, const int* in_sizes, int n_in,
                              void* d_out, int out_size)
{
    const float* x     = (const float*)d_in[0];
    const float* w     = (const float*)d_in[1];
    const float* gamma = (const float*)d_in[2];
    const float* beta  = (const float*)d_in[3];
    const float* mean  = (const float*)d_in[4];
    const float* var   = (const float*)d_in[5];
    const float* dw    = (const float*)d_in[6];
    const float* scale = (const float*)d_in[7];

    k_reduce<<<dim3(256, 2), 128>>>(x, w, gamma, var);
    k_head<<<dim3(64 / TW, 64 / TH, B_), 256>>>(gamma, beta, mean, var,
                                                dw, scale, (float*)d_out);
}

// round 15
// speedup vs baseline: 1.4447x; 1.4447x over previous
#include <cuda_runtime.h>
#include <cstdint>

#define B_   16
#define CIN  256
#define CR   32
#define HW   4096          // 64*64
#define COUT 560           // 32 + 528

// 8 MB scratch: relu(BN(1x1conv(x)))
__device__ float g_z[B_ * CR * HW];

__device__ __forceinline__ uint32_t f2tf32(float v) {
    uint32_t r;
    asm("cvt.rna.tf32.f32 %0, %1;" : "=r"(r) : "f"(v));
    return r;
}

// ---------------------------------------------------------------------------
// Kernel 1: 1x1 reduce conv via warp-level mma.sync tf32 (HMMA fallback on
// Blackwell — family-portable PTX, unlike tcgen05).
// 512 blocks x 256 thr.  Block = 128 px; warp = 16 px x 32 ch x K=256.
// x streamed in 32-k chunks through smem; B pre-swizzled into fragment order.
// ---------------------------------------------------------------------------
#define XS_PAD 136                           // bank-conflict-free A-frag LDS
#define SM_XS  0                             // uint32 xs[32][136]  (17408 B)
#define SM_BF  (32 * XS_PAD * 4)             // uint32 bf[32][4][32][2] (32768 B)
#define SM_MISC (SM_BF + 32768)              // inv[32], bias[32]
#define SM_TOT  (SM_MISC + 256)

__global__ __launch_bounds__(256) void k_reduce_mma(
    const float* __restrict__ x, const float* __restrict__ w,
    const float* __restrict__ gamma, const float* __restrict__ beta,
    const float* __restrict__ mean,  const float* __restrict__ var)
{
    extern __shared__ __align__(16) char sm[];
    uint32_t* xs     = reinterpret_cast<uint32_t*>(sm + SM_XS);
    uint32_t* bf     = reinterpret_cast<uint32_t*>(sm + SM_BF);
    float*    inv_s  = reinterpret_cast<float*>(sm + SM_MISC);
    float*    bias_s = inv_s + 32;

    const int tid  = threadIdx.x;
    const int lane = tid & 31;
    const int wid  = tid >> 5;

    if (tid < CR) {
        float inv = gamma[tid] * rsqrtf(var[tid] + 1e-5f);
        inv_s[tid]  = inv;
        bias_s[tid] = beta[tid] - mean[tid] * inv;
    }
    __syncthreads();

    // ---- build B fragments: bf[ksg][nt][lane][r] = tf32(w[ch][k] * inv[ch])
    //      k = ksg*8 + (lane&3) + 4r, ch = nt*8 + (lane>>2)
    for (int idx = tid; idx < 8192; idx += 256) {
        int r   = idx & 1;
        int ln  = (idx >> 1) & 31;
        int nt  = (idx >> 6) & 3;
        int ksg = idx >> 8;
        int k   = ksg * 8 + (ln & 3) + r * 4;
        int ch  = nt * 8 + (ln >> 2);
        bf[idx] = f2tf32(w[ch * CIN + k] * inv_s[ch]);
    }
    __syncthreads();

    const int pxb = blockIdx.x * 128;
    const int b   = pxb >> 12;
    const int s0  = pxb & 4095;
    const float* xp = x + (((size_t)b * CIN) << 12) + s0;

    float d[4][4];
#pragma unroll
    for (int nt = 0; nt < 4; nt++)
#pragma unroll
        for (int r = 0; r < 4; r++) d[nt][r] = 0.f;

    const int g  = lane >> 2;                // 0..7
    const int t4 = lane & 3;                 // 0..3
    const int pxl = wid * 16 + g;            // A-frag row (pixel)

    for (int kc = 0; kc < 8; kc++) {
        // ---- load 32-k chunk: pass i, row k_local = i*8 + wid ----
#pragma unroll
        for (int i = 0; i < 4; i++) {
            const int kl = i * 8 + wid;
            const int kg = kc * 32 + kl;
            float4 v = *reinterpret_cast<const float4*>(
                xp + ((size_t)kg << 12) + lane * 4);
            uint4 c;
            c.x = f2tf32(v.x); c.y = f2tf32(v.y);
            c.z = f2tf32(v.z); c.w = f2tf32(v.w);
            *reinterpret_cast<uint4*>(&xs[kl * XS_PAD + lane * 4]) = c;
        }
        __syncthreads();

        // ---- 4 K-steps of 8 ----
#pragma unroll
        for (int ks = 0; ks < 4; ks++) {
            const int k0 = ks * 8 + t4;
            uint32_t a0 = xs[k0 * XS_PAD + pxl];
            uint32_t a1 = xs[k0 * XS_PAD + pxl + 8];
            uint32_t a2 = xs[(k0 + 4) * XS_PAD + pxl];
            uint32_t a3 = xs[(k0 + 4) * XS_PAD + pxl + 8];
            const int ksg = kc * 4 + ks;
#pragma unroll
            for (int nt = 0; nt < 4; nt++) {
                uint2 bb = *reinterpret_cast<const uint2*>(
                    bf + ((ksg * 4 + nt) * 32 + lane) * 2);
                asm volatile(
                    "mma.sync.aligned.m16n8k8.row.col.f32.tf32.tf32.f32 "
                    "{%0,%1,%2,%3}, {%4,%5,%6,%7}, {%8,%9}, {%0,%1,%2,%3};"
                    : "+f"(d[nt][0]), "+f"(d[nt][1]),
                      "+f"(d[nt][2]), "+f"(d[nt][3])
                    : "r"(a0), "r"(a1), "r"(a2), "r"(a3),
                      "r"(bb.x), "r"(bb.y));
            }
        }
        __syncthreads();
    }

    // ---- epilogue: bias + ReLU + scatter to g_z[ch][px] ----
    float* zp = g_z + (((size_t)b * CR) << 12) + s0 + pxl;
#pragma unroll
    for (int nt = 0; nt < 4; nt++) {
        const int ch = nt * 8 + t4 * 2;
        const float b0 = bias_s[ch], b1 = bias_s[ch + 1];
        zp[((size_t)ch << 12)]           = fmaxf(d[nt][0] + b0, 0.f);
        zp[((size_t)(ch + 1) << 12)]     = fmaxf(d[nt][1] + b1, 0.f);
        zp[((size_t)ch << 12) + 8]       = fmaxf(d[nt][2] + b0, 0.f);
        zp[((size_t)(ch + 1) << 12) + 8] = fmaxf(d[nt][3] + b1, 0.f);
    }
}

// ---------------------------------------------------------------------------
// Kernel 2 (measured 29.7us, unchanged): depthwise 3x3 + scale, dual
// L2-normalize, triu pairs, concat.  32x4 tile, 256 threads.
// ---------------------------------------------------------------------------
#define TW 32
#define TH 4
#define ROWW 34
#define NPX  204
#define CH_STRIDE NPX

__global__ __launch_bounds__(256, 4) void k_head(
    const float* __restrict__ dw, const float* __restrict__ scale,
    float* __restrict__ out)
{
    __shared__ float zt[CR * CH_STRIDE];
    __shared__ __align__(16) float zc_s[CR * 128];
    __shared__ float ssz_s[2][128];
    __shared__ float sst_s[2][128];
    __shared__ __align__(16) float invz_s[128];
    __shared__ __align__(16) float invt_s[128];
    __shared__ float dws[CR * 9];
    __shared__ float sc_s[CR];

    const int tid  = threadIdx.x;
    const int lane = tid & 31;
    const int wid  = tid >> 5;
    const int b    = blockIdx.z;
    const int ty0  = blockIdx.y * TH;
    const int tx0  = blockIdx.x * TW;
    const int half = tid >> 7;
    const int p    = tid & 127;
    const int pty  = p >> 5;
    const int ptx  = p & 31;

    if (tid < CR) sc_s[tid] = scale[tid];
    for (int i = tid; i < CR * 9; i += 256) dws[i] = dw[i];

    int  offs[7];
    bool vld[7];
#pragma unroll
    for (int it = 0; it < 7; it++) {
        int px = it * 32 + lane;
        int y  = px / ROWW;
        int xx = px - y * ROWW;
        int gy = ty0 - 1 + y;
        int gx = tx0 - 1 + xx;
        vld[it]  = (px < NPX) && ((unsigned)gy < 64u) && ((unsigned)gx < 64u);
        offs[it] = (gy << 6) + gx;
    }
    const float* zb = g_z + (((size_t)b * CR) << 12);
#pragma unroll
    for (int cc = 0; cc < 4; cc++) {
        const int c = cc * 8 + wid;
        const float* zc0 = zb + ((size_t)c << 12);
        float* st = zt + c * CH_STRIDE;
#pragma unroll
        for (int it = 0; it < 7; it++) {
            float v = vld[it] ? __ldg(zc0 + offs[it]) : 0.f;
            int px = it * 32 + lane;
            if (px < NPX) st[px] = v;
        }
    }
    __syncthreads();

    {
        float ssz = 0.f, sst = 0.f;
        const int cBase = half * 16;
#pragma unroll
        for (int cc = 0; cc < 16; cc++) {
            const int c = cBase + cc;
            const float* pp = zt + c * CH_STRIDE + pty * ROWW + ptx;
            const float* k9 = dws + c * 9;
            float acc;
            acc = pp[0] * k9[0];
            acc = fmaf(pp[1],            k9[1], acc);
            acc = fmaf(pp[2],            k9[2], acc);
            acc = fmaf(pp[ROWW],         k9[3], acc);
            float ctr = pp[ROWW + 1];
            acc = fmaf(ctr,              k9[4], acc);
            acc = fmaf(pp[ROWW + 2],     k9[5], acc);
            acc = fmaf(pp[2 * ROWW],     k9[6], acc);
            acc = fmaf(pp[2 * ROWW + 1], k9[7], acc);
            acc = fmaf(pp[2 * ROWW + 2], k9[8], acc);
            acc *= sc_s[c];
            zc_s[c * 128 + p] = acc;
            ssz = fmaf(ctr, ctr, ssz);
            sst = fmaf(acc, acc, sst);
        }
        ssz_s[half][p] = ssz;
        sst_s[half][p] = sst;
    }
    __syncthreads();

    {
        const float fz = ssz_s[0][p] + ssz_s[1][p];
        const float ft = sst_s[0][p] + sst_s[1][p];
        invz_s[p] = 1.f / fmaxf(sqrtf(fz), 1e-6f);
        invt_s[p] = 1.f / fmaxf(sqrtf(ft), 1e-6f);
    }
    __syncthreads();

    const int e  = wid;
    const int g  = lane;
    const int gy = g >> 3;
    const int gx = (g & 7) * 4;
    const int p0 = gy * 32 + gx;

    const float4 iz4 = *reinterpret_cast<const float4*>(&invz_s[p0]);
    const float4 it4 = *reinterpret_cast<const float4*>(&invt_s[p0]);

    const int s = ((ty0 + gy) << 6) + tx0 + gx;
    float* op = out + (size_t)b * COUT * HW + s;
    const float* ctr = zt + gy * ROWW + gx + ROWW + 1;

    int ch = 70 * e;
    const int chHi = ch + 70;

    for (; ch < 32 && ch < chHi; ch++) {
        const float* zz = ctr + ch * CH_STRIDE;
        float4 o;
        o.x = zz[0] * iz4.x;
        o.y = zz[1] * iz4.y;
        o.z = zz[2] * iz4.z;
        o.w = zz[3] * iz4.w;
        *reinterpret_cast<float4*>(op + (size_t)ch * HW) = o;
    }

    if (ch < chHi) {
        int k = ch - 32;
        int i = 0;
        while (32 * (i + 1) - ((i + 1) * i) / 2 <= k) i++;
        int j = i + (k - (32 * i - (i * (i - 1)) / 2));

        float4 s4;
        s4.x = iz4.x * it4.x;
        s4.y = iz4.y * it4.y;
        s4.z = iz4.z * it4.z;
        s4.w = iz4.w * it4.w;

        const float* zz = ctr + i * CH_STRIDE;
        float4 zin;
        zin.x = zz[0] * s4.x;
        zin.y = zz[1] * s4.y;
        zin.z = zz[2] * s4.z;
        zin.w = zz[3] * s4.w;

        float* pdst = op + (size_t)ch * HW;
#pragma unroll 4
        for (; ch < chHi; ch++) {
            float4 zj = *reinterpret_cast<const float4*>(&zc_s[j * 128 + p0]);
            float4 o;
            o.x = zin.x * zj.x;
            o.y = zin.y * zj.y;
            o.z = zin.z * zj.z;
            o.w = zin.w * zj.w;
            *reinterpret_cast<float4*>(pdst) = o;
            pdst += HW;
            if (++j == CR) {
                ++i;
                j = i;
                if (i < CR) {
                    const float* z2 = ctr + i * CH_STRIDE;
                    zin.x = z2[0] * s4.x;
                    zin.y = z2[1] * s4.y;
                    zin.z = z2[2] * s4.z;
                    zin.w = z2[3] * s4.w;
                }
            }
        }
    }
}

extern "C" void kernel_launch(void* const* d_in, const int* in_sizes, int n_in,
                              void* d_out, int out_size)
{
    const float* x     = (const float*)d_in[0];
    const float* w     = (const float*)d_in[1];
    const float* gamma = (const float*)d_in[2];
    const float* beta  = (const float*)d_in[3];
    const float* mean  = (const float*)d_in[4];
    const float* var   = (const float*)d_in[5];
    const float* dw    = (const float*)d_in[6];
    const float* scale = (const float*)d_in[7];

    cudaFuncSetAttribute(k_reduce_mma,
                         cudaFuncAttributeMaxDynamicSharedMemorySize, SM_TOT);
    k_reduce_mma<<<512, 256, SM_TOT>>>(x, w, gamma, beta, mean, var);
    k_head<<<dim3(64 / TW, 64 / TH, B_), 256>>>(dw, scale, (float*)d_out);
}